// round 12
// baseline (speedup 1.0000x reference)
#include <cuda_runtime.h>
#include <cuda_fp16.h>
#include <cstdint>

#define T_TOK 8192
#define HID   1536
#define NEXP  32
#define TOPK  8
#define INTER 512
#define N1    (2*INTER)       // 1024
#define MAXP  (T_TOK*TOPK)    // 65536

#define KSLAB 64
#define STG   49152           // Ah16K + Bh32K
#define SMEMG (1024 + 4*STG)  // 197632

// ---------------- device scratch ----------------
__device__ int   g_counts[NEXP];
__device__ int   g_list[NEXP * T_TOK];
__device__ float g_pairw[MAXP];
__device__ float g_logits[(size_t)T_TOK * NEXP];
__device__ __half g_xh[(size_t)T_TOK * HID];
__device__ __half g_w13h[(size_t)NEXP * N1 * HID];
__device__ __half g_w2h[(size_t)NEXP * HID * INTER];
__device__ __half g_hh[(size_t)MAXP * INTER];
__device__ __half g_y[(size_t)MAXP * HID];

// ---------------- PTX helpers (sm_103-baseline safe) ----------------
__device__ __forceinline__ uint32_t smem_u32(const void* p) {
    uint32_t a;
    asm("{ .reg .u64 t; cvta.to.shared.u64 t, %1; cvt.u32.u64 %0, t; }" : "=r"(a) : "l"(p));
    return a;
}
__device__ __forceinline__ uint32_t swz(uint32_t b) { return b ^ ((b >> 3) & 0x70); }

__device__ __forceinline__ void cp16(uint32_t dst, const void* src, bool valid) {
    int sz = valid ? 16 : 0;
    asm volatile("cp.async.cg.shared.global [%0], [%1], 16, %2;\n" :: "r"(dst), "l"(src), "r"(sz));
}
__device__ __forceinline__ void cp_commit() { asm volatile("cp.async.commit_group;" ::: "memory"); }
template <int N> __device__ __forceinline__ void cp_wait() {
    asm volatile("cp.async.wait_group %0;" :: "n"(N) : "memory");
}
__device__ __forceinline__ void ldsm4(uint32_t* r, uint32_t addr) {
    asm volatile("ldmatrix.sync.aligned.m8n8.x4.shared.b16 {%0,%1,%2,%3}, [%4];"
                 : "=r"(r[0]), "=r"(r[1]), "=r"(r[2]), "=r"(r[3]) : "r"(addr));
}
__device__ __forceinline__ void mma_f16(float* c, const uint32_t* a, const uint32_t* b) {
    asm volatile("mma.sync.aligned.m16n8k16.row.col.f32.f16.f16.f32 "
                 "{%0,%1,%2,%3}, {%4,%5,%6,%7}, {%8,%9}, {%0,%1,%2,%3};"
                 : "+f"(c[0]), "+f"(c[1]), "+f"(c[2]), "+f"(c[3])
                 : "r"(a[0]), "r"(a[1]), "r"(a[2]), "r"(a[3]), "r"(b[0]), "r"(b[1]));
}

// ---------------- reset ----------------
__global__ void reset_kernel() {
    if (threadIdx.x < NEXP) g_counts[threadIdx.x] = 0;
}

// ---------------- fp32 -> fp16 for BOTH weight tensors (one launch) ----------------
__global__ void cvt_w_all(const float* __restrict__ w13, const float* __restrict__ w2) {
    const int n13 = NEXP * N1 * HID / 4;
    const int n2  = NEXP * HID * INTER / 4;
    int i = blockIdx.x * blockDim.x + threadIdx.x;
    const float4* src;
    uint2* dst;
    int j;
    if (i < n13) { src = (const float4*)w13; dst = (uint2*)g_w13h; j = i; }
    else if (i < n13 + n2) { src = (const float4*)w2; dst = (uint2*)g_w2h; j = i - n13; }
    else return;
    float4 v = src[j];
    __half h0 = __float2half_rn(v.x), h1 = __float2half_rn(v.y);
    __half h2 = __float2half_rn(v.z), h3 = __float2half_rn(v.w);
    uint2 hv;
    hv.x = (uint32_t)*reinterpret_cast<unsigned short*>(&h0) | ((uint32_t)*reinterpret_cast<unsigned short*>(&h1) << 16);
    hv.y = (uint32_t)*reinterpret_cast<unsigned short*>(&h2) | ((uint32_t)*reinterpret_cast<unsigned short*>(&h3) << 16);
    dst[j] = hv;
}

// ---------------- Logits GEMM: C[8192,32] = x @ gw^T (fp32 SIMT, smem-tiled) ----------------
// CTA: 128 tokens x 32 experts, K-slab 64. 256 threads = 32(tx) x 8(ty), microtile 4tok x 4exp.
// Also emits fp16 x (fused cvt_x).
__global__ __launch_bounds__(256) void logits_kernel(const float* __restrict__ x,
                                                     const float* __restrict__ gw) {
    __shared__ float xs[64][132];   // [k][tok]
    __shared__ float gs[64][36];    // [k][exp]

    const int t0 = blockIdx.x * 128;
    const int tid = threadIdx.x;
    const int tx = tid & 31, ty = tid >> 5;

    float acc[4][4];
    #pragma unroll
    for (int i = 0; i < 4; i++)
        #pragma unroll
        for (int j = 0; j < 4; j++) acc[i][j] = 0.f;

    for (int k0 = 0; k0 < HID; k0 += 64) {
        __syncthreads();
        // load x slab: 128 tok x 64 k = 2048 float4, 8 per thread; emit fp16 x alongside
        #pragma unroll
        for (int i = 0; i < 8; i++) {
            int idx = tid + i * 256;          // 0..2047
            int tok = idx >> 4, kq = idx & 15;
            float4 v = *(const float4*)(x + (size_t)(t0 + tok) * HID + k0 + kq * 4);
            xs[kq * 4 + 0][tok] = v.x;
            xs[kq * 4 + 1][tok] = v.y;
            xs[kq * 4 + 2][tok] = v.z;
            xs[kq * 4 + 3][tok] = v.w;
            __half h0 = __float2half_rn(v.x), h1 = __float2half_rn(v.y);
            __half h2 = __float2half_rn(v.z), h3 = __float2half_rn(v.w);
            uint2 hv;
            hv.x = (uint32_t)*reinterpret_cast<unsigned short*>(&h0) | ((uint32_t)*reinterpret_cast<unsigned short*>(&h1) << 16);
            hv.y = (uint32_t)*reinterpret_cast<unsigned short*>(&h2) | ((uint32_t)*reinterpret_cast<unsigned short*>(&h3) << 16);
            *(uint2*)(g_xh + (size_t)(t0 + tok) * HID + k0 + kq * 4) = hv;
        }
        // load gw slab: 32 exp x 64 k = 512 float4, 2 per thread
        #pragma unroll
        for (int i = 0; i < 2; i++) {
            int idx = tid + i * 256;          // 0..511
            int e = idx >> 4, kq = idx & 15;
            float4 v = *(const float4*)(gw + (size_t)e * HID + k0 + kq * 4);
            gs[kq * 4 + 0][e] = v.x;
            gs[kq * 4 + 1][e] = v.y;
            gs[kq * 4 + 2][e] = v.z;
            gs[kq * 4 + 3][e] = v.w;
        }
        __syncthreads();
        #pragma unroll
        for (int k = 0; k < 64; k++) {
            float4 xv = *(const float4*)&xs[k][tx * 4];
            float4 gv = *(const float4*)&gs[k][ty * 4];
            acc[0][0] += xv.x * gv.x; acc[0][1] += xv.x * gv.y; acc[0][2] += xv.x * gv.z; acc[0][3] += xv.x * gv.w;
            acc[1][0] += xv.y * gv.x; acc[1][1] += xv.y * gv.y; acc[1][2] += xv.y * gv.z; acc[1][3] += xv.y * gv.w;
            acc[2][0] += xv.z * gv.x; acc[2][1] += xv.z * gv.y; acc[2][2] += xv.z * gv.z; acc[2][3] += xv.z * gv.w;
            acc[3][0] += xv.w * gv.x; acc[3][1] += xv.w * gv.y; acc[3][2] += xv.w * gv.z; acc[3][3] += xv.w * gv.w;
        }
    }

    #pragma unroll
    for (int i = 0; i < 4; i++) {
        int t = t0 + tx * 4 + i;
        float4 o = make_float4(acc[i][0], acc[i][1], acc[i][2], acc[i][3]);
        *(float4*)(g_logits + (size_t)t * NEXP + ty * 4) = o;
    }
}

// ---------------- Top-k: one warp per token, reads precomputed logits ----------------
__global__ __launch_bounds__(256) void topk_kernel() {
    const unsigned FULL = 0xffffffffu;
    int warp = (blockIdx.x * blockDim.x + threadIdx.x) >> 5;
    int lane = threadIdx.x & 31;
    if (warp >= T_TOK) return;
    const int t = warp;

    float logit = g_logits[(size_t)t * NEXP + lane];

    float m = logit;
    #pragma unroll
    for (int off = 16; off; off >>= 1) m = fmaxf(m, __shfl_xor_sync(FULL, m, off));
    float p = expf(logit - m);
    float sum = p;
    #pragma unroll
    for (int off = 16; off; off >>= 1) sum += __shfl_xor_sync(FULL, sum, off);
    p = p / sum;

    float keep = p, topsum = 0.f;
    int myslot = -1;
    for (int s = 0; s < TOPK; s++) {
        float v = keep; int bl = lane;
        #pragma unroll
        for (int off = 16; off; off >>= 1) {
            float ov = __shfl_down_sync(FULL, v, off);
            int   ol = __shfl_down_sync(FULL, bl, off);
            if (ov > v || (ov == v && ol < bl)) { v = ov; bl = ol; }
        }
        bl = __shfl_sync(FULL, bl, 0);
        v  = __shfl_sync(FULL, v, 0);
        topsum += v;
        if (lane == bl) { myslot = s; keep = -1.f; }
    }
    if (myslot >= 0) {
        int pos = atomicAdd(&g_counts[lane], 1);
        g_list[lane * T_TOK + pos] = t * TOPK + myslot;
        g_pairw[t * TOPK + myslot] = p / topsum;
    }
}

// ================= GEMM1: x(fp16) @ w13(fp16)^T, single-pass, fused SiLU =================
// CTA 128(M) x 256(N=128 gate + 128 up), K-slab 64, 4-stage, SW128 (128B rows).
__global__ __launch_bounds__(256, 1) void gemm1_mma() {
    const int e  = blockIdx.z;
    const int M  = g_counts[e];
    const int m0 = blockIdx.y * 128;
    if (m0 >= M) return;
    const int t = blockIdx.x;   // 0..3

    extern __shared__ char dsm[];
    int* s_pair = (int*)dsm;
    const uint32_t TILE = smem_u32(dsm) + 1024;
    float* sC = (float*)(dsm + 1024);

    const int tid = threadIdx.x, wid = tid >> 5, lane = tid & 31;
    const int warp_m = wid >> 2, warp_n = wid & 3;

    if (tid < 128) {
        int gr = m0 + tid;
        s_pair[tid] = (gr < M) ? g_list[e * T_TOK + gr] : -1;
    }
    __syncthreads();

    uint32_t offA[4], dstA[4]; bool vA[4];
    uint32_t offB[8], dstB[8];
    #pragma unroll
    for (int i = 0; i < 4; i++) {
        int c = tid + i * 256, r = c >> 3, cw = c & 7;
        int p = s_pair[r];
        vA[i] = (p >= 0);
        offA[i] = (uint32_t)(vA[i] ? (p >> 3) : 0) * HID + cw * 8;
        dstA[i] = swz(r * 128 + cw * 16);
    }
    #pragma unroll
    for (int i = 0; i < 8; i++) {
        int c = tid + i * 256, r = c >> 3, cw = c & 7;
        int brow = (r < 128) ? (t * 128 + r) : (512 + t * 128 + (r - 128));
        offB[i] = ((uint32_t)e * N1 + brow) * HID + cw * 8;
        dstB[i] = swz(r * 128 + cw * 16);
    }

    auto load_stage = [&](int b, int k0) {
        uint32_t st = TILE + b * STG;
        #pragma unroll
        for (int i = 0; i < 4; i++)
            cp16(st + dstA[i], g_xh + offA[i] + k0, vA[i]);
        #pragma unroll
        for (int i = 0; i < 8; i++)
            cp16(st + 16384 + dstB[i], g_w13h + offB[i] + k0, true);
        cp_commit();
    };

    float acc[4][8][4];
    #pragma unroll
    for (int m = 0; m < 4; m++)
        #pragma unroll
        for (int n = 0; n < 8; n++)
            #pragma unroll
            for (int k = 0; k < 4; k++) acc[m][n][k] = 0.f;

    const uint32_t a_row = warp_m * 64 + (lane & 15);
    const uint32_t a_kb  = (lane >> 4) * 16;
    const uint32_t b_row = warp_n * 64 + (lane & 7) + ((lane >> 4) << 3);
    const uint32_t b_kb  = ((lane >> 3) & 1) * 16;

    const int S = HID / KSLAB;  // 24
    load_stage(0, 0);
    load_stage(1, KSLAB);
    load_stage(2, 2 * KSLAB);
    for (int s = 0; s < S; s++) {
        if (s + 2 < S) cp_wait<2>(); else if (s + 1 < S) cp_wait<1>(); else cp_wait<0>();
        __syncthreads();
        if (s + 3 < S) load_stage((s + 3) & 3, (s + 3) * KSLAB);
        const uint32_t st = TILE + (s & 3) * STG;
        const uint32_t sAh = st, sBh = st + 16384;
        #pragma unroll
        for (int ks = 0; ks < 4; ks++) {
            uint32_t ah[4][4];
            #pragma unroll
            for (int m = 0; m < 4; m++) {
                uint32_t off = (a_row + m * 16) * 128 + ks * 32 + a_kb;
                ldsm4(ah[m], sAh + swz(off));
            }
            #pragma unroll
            for (int j = 0; j < 4; j++) {
                uint32_t off = (b_row + j * 16) * 128 + ks * 32 + b_kb;
                uint32_t th[4];
                ldsm4(th, sBh + swz(off));
                #pragma unroll
                for (int m = 0; m < 4; m++) {
                    mma_f16(acc[m][2*j],   ah[m], th);
                    mma_f16(acc[m][2*j+1], ah[m], th + 2);
                }
            }
        }
    }
    __syncthreads();

    // ---- fused epilogue: gate warps (warp_n<2) stage C via smem; up warps emit fp16 h ----
    const int g = lane >> 2, tg = lane & 3;
    if (warp_n < 2) {
        #pragma unroll
        for (int m = 0; m < 4; m++) {
            int row = warp_m * 64 + m * 16 + g;
            #pragma unroll
            for (int n = 0; n < 8; n++) {
                int col = warp_n * 64 + n * 8 + tg * 2;
                sC[row * 132 + col]           = acc[m][n][0];
                sC[row * 132 + col + 1]       = acc[m][n][1];
                sC[(row + 8) * 132 + col]     = acc[m][n][2];
                sC[(row + 8) * 132 + col + 1] = acc[m][n][3];
            }
        }
    }
    __syncthreads();
    if (warp_n >= 2) {
        #pragma unroll
        for (int m = 0; m < 4; m++) {
            int row = warp_m * 64 + m * 16 + g;
            int p0 = s_pair[row], p1 = s_pair[row + 8];
            #pragma unroll
            for (int n = 0; n < 8; n++) {
                int ucol = (warp_n - 2) * 64 + n * 8 + tg * 2;
                if (p0 >= 0) {
                    float g0 = sC[row * 132 + ucol], g1 = sC[row * 132 + ucol + 1];
                    float h0 = g0 / (1.f + expf(-g0)) * acc[m][n][0];
                    float h1 = g1 / (1.f + expf(-g1)) * acc[m][n][1];
                    __half b0 = __float2half_rn(h0), b1 = __float2half_rn(h1);
                    uint32_t o = ((uint32_t)p0 * INTER + t * 128 + ucol) >> 1;
                    ((uint32_t*)g_hh)[o] = (uint32_t)*reinterpret_cast<unsigned short*>(&b0) |
                                           ((uint32_t)*reinterpret_cast<unsigned short*>(&b1) << 16);
                }
                if (p1 >= 0) {
                    float g0 = sC[(row + 8) * 132 + ucol], g1 = sC[(row + 8) * 132 + ucol + 1];
                    float h0 = g0 / (1.f + expf(-g0)) * acc[m][n][2];
                    float h1 = g1 / (1.f + expf(-g1)) * acc[m][n][3];
                    __half b0 = __float2half_rn(h0), b1 = __float2half_rn(h1);
                    uint32_t o = ((uint32_t)p1 * INTER + t * 128 + ucol) >> 1;
                    ((uint32_t*)g_hh)[o] = (uint32_t)*reinterpret_cast<unsigned short*>(&b0) |
                                           ((uint32_t)*reinterpret_cast<unsigned short*>(&b1) << 16);
                }
            }
        }
    }
}

// ================= GEMM2: h(fp16) @ w2(fp16)^T, single-pass, scaled, fp16 y =================
__global__ __launch_bounds__(256, 1) void gemm2_mma() {
    const int e  = blockIdx.z;
    const int M  = g_counts[e];
    const int m0 = blockIdx.y * 128;
    if (m0 >= M) return;
    const int n0 = blockIdx.x * 256;

    extern __shared__ char dsm[];
    int* s_pair = (int*)dsm;
    const uint32_t TILE = smem_u32(dsm) + 1024;

    const int tid = threadIdx.x, wid = tid >> 5, lane = tid & 31;
    const int warp_m = wid >> 2, warp_n = wid & 3;

    if (tid < 128) {
        int gr = m0 + tid;
        s_pair[tid] = (gr < M) ? g_list[e * T_TOK + gr] : -1;
    }
    __syncthreads();

    uint32_t offA[4], dstA[4]; bool vA[4];
    uint32_t offB[8], dstB[8];
    #pragma unroll
    for (int i = 0; i < 4; i++) {
        int c = tid + i * 256, r = c >> 3, cw = c & 7;
        int p = s_pair[r];
        vA[i] = (p >= 0);
        offA[i] = (uint32_t)(vA[i] ? p : 0) * INTER + cw * 8;
        dstA[i] = swz(r * 128 + cw * 16);
    }
    #pragma unroll
    for (int i = 0; i < 8; i++) {
        int c = tid + i * 256, r = c >> 3, cw = c & 7;
        offB[i] = ((uint32_t)e * HID + n0 + r) * INTER + cw * 8;
        dstB[i] = swz(r * 128 + cw * 16);
    }

    auto load_stage = [&](int b, int k0) {
        uint32_t st = TILE + b * STG;
        #pragma unroll
        for (int i = 0; i < 4; i++)
            cp16(st + dstA[i], g_hh + offA[i] + k0, vA[i]);
        #pragma unroll
        for (int i = 0; i < 8; i++)
            cp16(st + 16384 + dstB[i], g_w2h + offB[i] + k0, true);
        cp_commit();
    };

    float acc[4][8][4];
    #pragma unroll
    for (int m = 0; m < 4; m++)
        #pragma unroll
        for (int n = 0; n < 8; n++)
            #pragma unroll
            for (int k = 0; k < 4; k++) acc[m][n][k] = 0.f;

    const uint32_t a_row = warp_m * 64 + (lane & 15);
    const uint32_t a_kb  = (lane >> 4) * 16;
    const uint32_t b_row = warp_n * 64 + (lane & 7) + ((lane >> 4) << 3);
    const uint32_t b_kb  = ((lane >> 3) & 1) * 16;

    const int S = INTER / KSLAB;  // 8
    load_stage(0, 0);
    load_stage(1, KSLAB);
    load_stage(2, 2 * KSLAB);
    for (int s = 0; s < S; s++) {
        if (s + 2 < S) cp_wait<2>(); else if (s + 1 < S) cp_wait<1>(); else cp_wait<0>();
        __syncthreads();
        if (s + 3 < S) load_stage((s + 3) & 3, (s + 3) * KSLAB);
        const uint32_t st = TILE + (s & 3) * STG;
        const uint32_t sAh = st, sBh = st + 16384;
        #pragma unroll
        for (int ks = 0; ks < 4; ks++) {
            uint32_t ah[4][4];
            #pragma unroll
            for (int m = 0; m < 4; m++) {
                uint32_t off = (a_row + m * 16) * 128 + ks * 32 + a_kb;
                ldsm4(ah[m], sAh + swz(off));
            }
            #pragma unroll
            for (int j = 0; j < 4; j++) {
                uint32_t off = (b_row + j * 16) * 128 + ks * 32 + b_kb;
                uint32_t th[4];
                ldsm4(th, sBh + swz(off));
                #pragma unroll
                for (int m = 0; m < 4; m++) {
                    mma_f16(acc[m][2*j],   ah[m], th);
                    mma_f16(acc[m][2*j+1], ah[m], th + 2);
                }
            }
        }
    }

    const int g = lane >> 2, tg = lane & 3;
    #pragma unroll
    for (int m = 0; m < 4; m++) {
        int lr = warp_m * 64 + m * 16 + g;
        int p0 = s_pair[lr], p1 = s_pair[lr + 8];
        float w0 = (p0 >= 0) ? g_pairw[p0] : 0.f;
        float w1 = (p1 >= 0) ? g_pairw[p1] : 0.f;
        #pragma unroll
        for (int n = 0; n < 8; n++) {
            int col = n0 + warp_n * 64 + n * 8 + tg * 2;
            if (p0 >= 0)
                ((__half2*)g_y)[((uint32_t)p0 * HID + col) >> 1] =
                    __floats2half2_rn(w0 * acc[m][n][0], w0 * acc[m][n][1]);
            if (p1 >= 0)
                ((__half2*)g_y)[((uint32_t)p1 * HID + col) >> 1] =
                    __floats2half2_rn(w1 * acc[m][n][2], w1 * acc[m][n][3]);
        }
    }
}

// ---------------- deterministic 8-slot reduction (fp16 in, fp32 out) ----------------
__global__ void reduce_kernel(float* __restrict__ out) {
    size_t idx = (size_t)blockIdx.x * blockDim.x + threadIdx.x;
    const size_t total = (size_t)T_TOK * (HID / 8);
    if (idx >= total) return;
    size_t t = idx / (HID / 8);
    int    c = (int)(idx % (HID / 8));
    const __half* base = g_y + t * (size_t)TOPK * HID + c * 8;
    float s[8] = {0.f, 0.f, 0.f, 0.f, 0.f, 0.f, 0.f, 0.f};
    #pragma unroll
    for (int sl = 0; sl < TOPK; sl++) {
        uint4 v = *(const uint4*)(base + (size_t)sl * HID);
        const __half2* h2 = (const __half2*)&v;
        #pragma unroll
        for (int j = 0; j < 4; j++) {
            float2 f = __half22float2(h2[j]);
            s[2*j]     += f.x;
            s[2*j + 1] += f.y;
        }
    }
    float4* o4 = (float4*)(out + t * HID + c * 8);
    o4[0] = make_float4(s[0], s[1], s[2], s[3]);
    o4[1] = make_float4(s[4], s[5], s[6], s[7]);
}

extern "C" void kernel_launch(void* const* d_in, const int* in_sizes, int n_in,
                              void* d_out, int out_size) {
    (void)in_sizes; (void)n_in; (void)out_size;
    const float* x   = (const float*)d_in[0];
    const float* gw  = (const float*)d_in[1];
    const float* w13 = (const float*)d_in[2];
    const float* w2  = (const float*)d_in[3];
    float* out = (float*)d_out;

    cudaFuncSetAttribute(gemm1_mma, cudaFuncAttributeMaxDynamicSharedMemorySize, SMEMG);
    cudaFuncSetAttribute(gemm2_mma, cudaFuncAttributeMaxDynamicSharedMemorySize, SMEMG);

    const int n_cvt = (NEXP * N1 * HID + NEXP * HID * INTER) / 4;
    reset_kernel<<<1, 32>>>();
    cvt_w_all<<<(n_cvt + 255) / 256, 256>>>(w13, w2);
    logits_kernel<<<T_TOK / 128, 256>>>(x, gw);
    topk_kernel<<<T_TOK / 8, 256>>>();
    gemm1_mma<<<dim3(INTER / 128, 64, NEXP), 256, SMEMG>>>();
    gemm2_mma<<<dim3(HID / 256, 64, NEXP), 256, SMEMG>>>();
    reduce_kernel<<<(int)(((size_t)T_TOK * (HID / 8)) / 256), 256>>>(out);
}

// round 14
// speedup vs baseline: 1.6090x; 1.6090x over previous
#include <cuda_runtime.h>
#include <cuda_fp16.h>
#include <cstdint>

#define T_TOK 8192
#define HID   1536
#define NEXP  32
#define TOPK  8
#define INTER 512
#define N1    (2*INTER)       // 1024
#define MAXP  (T_TOK*TOPK)    // 65536

#define KSLAB 64
#define STG   49152           // Ah16K + Bh32K
#define SMEMG (1024 + 4*STG)  // 197632

// ---------------- device scratch ----------------
__device__ int   g_counts[NEXP];
__device__ int   g_list[NEXP * T_TOK];
__device__ float g_pairw[MAXP];
__device__ float g_logits[(size_t)T_TOK * NEXP];
__device__ __half g_xh[(size_t)T_TOK * HID];
__device__ __half g_w13h[(size_t)NEXP * N1 * HID];
__device__ __half g_w2h[(size_t)NEXP * HID * INTER];
__device__ __half g_hh[(size_t)MAXP * INTER];
__device__ __half g_y[(size_t)MAXP * HID];

// ---------------- PTX helpers (sm_103-baseline safe) ----------------
__device__ __forceinline__ uint32_t smem_u32(const void* p) {
    uint32_t a;
    asm("{ .reg .u64 t; cvta.to.shared.u64 t, %1; cvt.u32.u64 %0, t; }" : "=r"(a) : "l"(p));
    return a;
}
__device__ __forceinline__ uint32_t swz(uint32_t b) { return b ^ ((b >> 3) & 0x70); }

__device__ __forceinline__ void cp16(uint32_t dst, const void* src, bool valid) {
    int sz = valid ? 16 : 0;
    asm volatile("cp.async.cg.shared.global [%0], [%1], 16, %2;\n" :: "r"(dst), "l"(src), "r"(sz));
}
__device__ __forceinline__ void cp_commit() { asm volatile("cp.async.commit_group;" ::: "memory"); }
template <int N> __device__ __forceinline__ void cp_wait() {
    asm volatile("cp.async.wait_group %0;" :: "n"(N) : "memory");
}
__device__ __forceinline__ void ldsm4(uint32_t* r, uint32_t addr) {
    asm volatile("ldmatrix.sync.aligned.m8n8.x4.shared.b16 {%0,%1,%2,%3}, [%4];"
                 : "=r"(r[0]), "=r"(r[1]), "=r"(r[2]), "=r"(r[3]) : "r"(addr));
}
__device__ __forceinline__ void mma_f16(float* c, const uint32_t* a, const uint32_t* b) {
    asm volatile("mma.sync.aligned.m16n8k16.row.col.f32.f16.f16.f32 "
                 "{%0,%1,%2,%3}, {%4,%5,%6,%7}, {%8,%9}, {%0,%1,%2,%3};"
                 : "+f"(c[0]), "+f"(c[1]), "+f"(c[2]), "+f"(c[3])
                 : "r"(a[0]), "r"(a[1]), "r"(a[2]), "r"(a[3]), "r"(b[0]), "r"(b[1]));
}

// ---------------- reset ----------------
__global__ void reset_kernel() {
    if (threadIdx.x < NEXP) g_counts[threadIdx.x] = 0;
}

// ---------------- fp32 -> fp16 conversions ----------------
__global__ void cvt_x_kernel(const float* __restrict__ x) {
    int i = blockIdx.x * blockDim.x + threadIdx.x;
    if (i >= T_TOK * HID / 4) return;
    float4 v = ((const float4*)x)[i];
    __half h0 = __float2half_rn(v.x), h1 = __float2half_rn(v.y);
    __half h2 = __float2half_rn(v.z), h3 = __float2half_rn(v.w);
    uint2 hv;
    hv.x = (uint32_t)*reinterpret_cast<unsigned short*>(&h0) | ((uint32_t)*reinterpret_cast<unsigned short*>(&h1) << 16);
    hv.y = (uint32_t)*reinterpret_cast<unsigned short*>(&h2) | ((uint32_t)*reinterpret_cast<unsigned short*>(&h3) << 16);
    ((uint2*)g_xh)[i] = hv;
}

__global__ void cvt_w_all(const float* __restrict__ w13, const float* __restrict__ w2) {
    const int n13 = NEXP * N1 * HID / 4;
    const int n2  = NEXP * HID * INTER / 4;
    int i = blockIdx.x * blockDim.x + threadIdx.x;
    const float4* src;
    uint2* dst;
    int j;
    if (i < n13) { src = (const float4*)w13; dst = (uint2*)g_w13h; j = i; }
    else if (i < n13 + n2) { src = (const float4*)w2; dst = (uint2*)g_w2h; j = i - n13; }
    else return;
    float4 v = src[j];
    __half h0 = __float2half_rn(v.x), h1 = __float2half_rn(v.y);
    __half h2 = __float2half_rn(v.z), h3 = __float2half_rn(v.w);
    uint2 hv;
    hv.x = (uint32_t)*reinterpret_cast<unsigned short*>(&h0) | ((uint32_t)*reinterpret_cast<unsigned short*>(&h1) << 16);
    hv.y = (uint32_t)*reinterpret_cast<unsigned short*>(&h2) | ((uint32_t)*reinterpret_cast<unsigned short*>(&h3) << 16);
    dst[j] = hv;
}

// ---------------- Logits GEMM: C[8192,32] = x @ gw^T (fp32, smem-tiled, lean) ----------------
// CTA: 64 tokens x 32 experts, K-slab 64. 256 threads = 32(tx) x 8(ty).
// Thread microtile: 2 tokens (tx, tx+32) x 4 experts (ty*4..ty*4+3). acc = 8 regs.
__global__ __launch_bounds__(256) void logits_kernel(const float* __restrict__ x,
                                                     const float* __restrict__ gw) {
    __shared__ float xs[64][68];   // [k][tok], 68-pad keeps 16B row alignment
    __shared__ float gs[64][36];   // [k][exp]

    const int t0 = blockIdx.x * 64;
    const int tid = threadIdx.x;
    const int tx = tid & 31, ty = tid >> 5;

    float a0[4] = {0.f, 0.f, 0.f, 0.f};
    float a1[4] = {0.f, 0.f, 0.f, 0.f};

    for (int k0 = 0; k0 < HID; k0 += 64) {
        __syncthreads();
        // x slab: 64 tok x 64 k = 1024 float4, 4 per thread
        #pragma unroll
        for (int i = 0; i < 4; i++) {
            int idx = tid + i * 256;          // 0..1023
            int tok = idx >> 4, kq = idx & 15;
            float4 v = *(const float4*)(x + (size_t)(t0 + tok) * HID + k0 + kq * 4);
            xs[kq * 4 + 0][tok] = v.x;
            xs[kq * 4 + 1][tok] = v.y;
            xs[kq * 4 + 2][tok] = v.z;
            xs[kq * 4 + 3][tok] = v.w;
        }
        // gw slab: 32 exp x 64 k = 512 float4, 2 per thread
        #pragma unroll
        for (int i = 0; i < 2; i++) {
            int idx = tid + i * 256;          // 0..511
            int e = idx >> 4, kq = idx & 15;
            float4 v = *(const float4*)(gw + (size_t)e * HID + k0 + kq * 4);
            gs[kq * 4 + 0][e] = v.x;
            gs[kq * 4 + 1][e] = v.y;
            gs[kq * 4 + 2][e] = v.z;
            gs[kq * 4 + 3][e] = v.w;
        }
        __syncthreads();
        #pragma unroll 8
        for (int k = 0; k < 64; k++) {
            float x0 = xs[k][tx];
            float x1 = xs[k][tx + 32];
            float4 gv = *(const float4*)&gs[k][ty * 4];
            a0[0] += x0 * gv.x; a0[1] += x0 * gv.y; a0[2] += x0 * gv.z; a0[3] += x0 * gv.w;
            a1[0] += x1 * gv.x; a1[1] += x1 * gv.y; a1[2] += x1 * gv.z; a1[3] += x1 * gv.w;
        }
    }

    *(float4*)(g_logits + (size_t)(t0 + tx) * NEXP + ty * 4)      = make_float4(a0[0], a0[1], a0[2], a0[3]);
    *(float4*)(g_logits + (size_t)(t0 + tx + 32) * NEXP + ty * 4) = make_float4(a1[0], a1[1], a1[2], a1[3]);
}

// ---------------- Top-k: one warp per token, reads precomputed logits ----------------
__global__ __launch_bounds__(256) void topk_kernel() {
    const unsigned FULL = 0xffffffffu;
    int warp = (blockIdx.x * blockDim.x + threadIdx.x) >> 5;
    int lane = threadIdx.x & 31;
    if (warp >= T_TOK) return;
    const int t = warp;

    float logit = g_logits[(size_t)t * NEXP + lane];

    float m = logit;
    #pragma unroll
    for (int off = 16; off; off >>= 1) m = fmaxf(m, __shfl_xor_sync(FULL, m, off));
    float p = expf(logit - m);
    float sum = p;
    #pragma unroll
    for (int off = 16; off; off >>= 1) sum += __shfl_xor_sync(FULL, sum, off);
    p = p / sum;

    float keep = p, topsum = 0.f;
    int myslot = -1;
    for (int s = 0; s < TOPK; s++) {
        float v = keep; int bl = lane;
        #pragma unroll
        for (int off = 16; off; off >>= 1) {
            float ov = __shfl_down_sync(FULL, v, off);
            int   ol = __shfl_down_sync(FULL, bl, off);
            if (ov > v || (ov == v && ol < bl)) { v = ov; bl = ol; }
        }
        bl = __shfl_sync(FULL, bl, 0);
        v  = __shfl_sync(FULL, v, 0);
        topsum += v;
        if (lane == bl) { myslot = s; keep = -1.f; }
    }
    if (myslot >= 0) {
        int pos = atomicAdd(&g_counts[lane], 1);
        g_list[lane * T_TOK + pos] = t * TOPK + myslot;
        g_pairw[t * TOPK + myslot] = p / topsum;
    }
}

// ================= GEMM1: x(fp16) @ w13(fp16)^T, single-pass, fused SiLU =================
// CTA 128(M) x 256(N=128 gate + 128 up), K-slab 64, 4-stage, SW128 (128B rows).
__global__ __launch_bounds__(256, 1) void gemm1_mma() {
    const int e  = blockIdx.z;
    const int M  = g_counts[e];
    const int m0 = blockIdx.y * 128;
    if (m0 >= M) return;
    const int t = blockIdx.x;   // 0..3

    extern __shared__ char dsm[];
    int* s_pair = (int*)dsm;
    const uint32_t TILE = smem_u32(dsm) + 1024;
    float* sC = (float*)(dsm + 1024);

    const int tid = threadIdx.x, wid = tid >> 5, lane = tid & 31;
    const int warp_m = wid >> 2, warp_n = wid & 3;

    if (tid < 128) {
        int gr = m0 + tid;
        s_pair[tid] = (gr < M) ? g_list[e * T_TOK + gr] : -1;
    }
    __syncthreads();

    uint32_t offA[4], dstA[4]; bool vA[4];
    uint32_t offB[8], dstB[8];
    #pragma unroll
    for (int i = 0; i < 4; i++) {
        int c = tid + i * 256, r = c >> 3, cw = c & 7;
        int p = s_pair[r];
        vA[i] = (p >= 0);
        offA[i] = (uint32_t)(vA[i] ? (p >> 3) : 0) * HID + cw * 8;
        dstA[i] = swz(r * 128 + cw * 16);
    }
    #pragma unroll
    for (int i = 0; i < 8; i++) {
        int c = tid + i * 256, r = c >> 3, cw = c & 7;
        int brow = (r < 128) ? (t * 128 + r) : (512 + t * 128 + (r - 128));
        offB[i] = ((uint32_t)e * N1 + brow) * HID + cw * 8;
        dstB[i] = swz(r * 128 + cw * 16);
    }

    auto load_stage = [&](int b, int k0) {
        uint32_t st = TILE + b * STG;
        #pragma unroll
        for (int i = 0; i < 4; i++)
            cp16(st + dstA[i], g_xh + offA[i] + k0, vA[i]);
        #pragma unroll
        for (int i = 0; i < 8; i++)
            cp16(st + 16384 + dstB[i], g_w13h + offB[i] + k0, true);
        cp_commit();
    };

    float acc[4][8][4];
    #pragma unroll
    for (int m = 0; m < 4; m++)
        #pragma unroll
        for (int n = 0; n < 8; n++)
            #pragma unroll
            for (int k = 0; k < 4; k++) acc[m][n][k] = 0.f;

    const uint32_t a_row = warp_m * 64 + (lane & 15);
    const uint32_t a_kb  = (lane >> 4) * 16;
    const uint32_t b_row = warp_n * 64 + (lane & 7) + ((lane >> 4) << 3);
    const uint32_t b_kb  = ((lane >> 3) & 1) * 16;

    const int S = HID / KSLAB;  // 24
    load_stage(0, 0);
    load_stage(1, KSLAB);
    load_stage(2, 2 * KSLAB);
    for (int s = 0; s < S; s++) {
        if (s + 2 < S) cp_wait<2>(); else if (s + 1 < S) cp_wait<1>(); else cp_wait<0>();
        __syncthreads();
        if (s + 3 < S) load_stage((s + 3) & 3, (s + 3) * KSLAB);
        const uint32_t st = TILE + (s & 3) * STG;
        const uint32_t sAh = st, sBh = st + 16384;
        #pragma unroll
        for (int ks = 0; ks < 4; ks++) {
            uint32_t ah[4][4];
            #pragma unroll
            for (int m = 0; m < 4; m++) {
                uint32_t off = (a_row + m * 16) * 128 + ks * 32 + a_kb;
                ldsm4(ah[m], sAh + swz(off));
            }
            #pragma unroll
            for (int j = 0; j < 4; j++) {
                uint32_t off = (b_row + j * 16) * 128 + ks * 32 + b_kb;
                uint32_t th[4];
                ldsm4(th, sBh + swz(off));
                #pragma unroll
                for (int m = 0; m < 4; m++) {
                    mma_f16(acc[m][2*j],   ah[m], th);
                    mma_f16(acc[m][2*j+1], ah[m], th + 2);
                }
            }
        }
    }
    __syncthreads();

    // ---- fused epilogue: gate warps (warp_n<2) stage C via smem; up warps emit fp16 h ----
    const int g = lane >> 2, tg = lane & 3;
    if (warp_n < 2) {
        #pragma unroll
        for (int m = 0; m < 4; m++) {
            int row = warp_m * 64 + m * 16 + g;
            #pragma unroll
            for (int n = 0; n < 8; n++) {
                int col = warp_n * 64 + n * 8 + tg * 2;
                sC[row * 132 + col]           = acc[m][n][0];
                sC[row * 132 + col + 1]       = acc[m][n][1];
                sC[(row + 8) * 132 + col]     = acc[m][n][2];
                sC[(row + 8) * 132 + col + 1] = acc[m][n][3];
            }
        }
    }
    __syncthreads();
    if (warp_n >= 2) {
        #pragma unroll
        for (int m = 0; m < 4; m++) {
            int row = warp_m * 64 + m * 16 + g;
            int p0 = s_pair[row], p1 = s_pair[row + 8];
            #pragma unroll
            for (int n = 0; n < 8; n++) {
                int ucol = (warp_n - 2) * 64 + n * 8 + tg * 2;
                if (p0 >= 0) {
                    float g0 = sC[row * 132 + ucol], g1 = sC[row * 132 + ucol + 1];
                    float h0 = g0 / (1.f + expf(-g0)) * acc[m][n][0];
                    float h1 = g1 / (1.f + expf(-g1)) * acc[m][n][1];
                    __half b0 = __float2half_rn(h0), b1 = __float2half_rn(h1);
                    uint32_t o = ((uint32_t)p0 * INTER + t * 128 + ucol) >> 1;
                    ((uint32_t*)g_hh)[o] = (uint32_t)*reinterpret_cast<unsigned short*>(&b0) |
                                           ((uint32_t)*reinterpret_cast<unsigned short*>(&b1) << 16);
                }
                if (p1 >= 0) {
                    float g0 = sC[(row + 8) * 132 + ucol], g1 = sC[(row + 8) * 132 + ucol + 1];
                    float h0 = g0 / (1.f + expf(-g0)) * acc[m][n][2];
                    float h1 = g1 / (1.f + expf(-g1)) * acc[m][n][3];
                    __half b0 = __float2half_rn(h0), b1 = __float2half_rn(h1);
                    uint32_t o = ((uint32_t)p1 * INTER + t * 128 + ucol) >> 1;
                    ((uint32_t*)g_hh)[o] = (uint32_t)*reinterpret_cast<unsigned short*>(&b0) |
                                           ((uint32_t)*reinterpret_cast<unsigned short*>(&b1) << 16);
                }
            }
        }
    }
}

// ================= GEMM2: h(fp16) @ w2(fp16)^T, single-pass, scaled, fp16 y =================
__global__ __launch_bounds__(256, 1) void gemm2_mma() {
    const int e  = blockIdx.z;
    const int M  = g_counts[e];
    const int m0 = blockIdx.y * 128;
    if (m0 >= M) return;
    const int n0 = blockIdx.x * 256;

    extern __shared__ char dsm[];
    int* s_pair = (int*)dsm;
    const uint32_t TILE = smem_u32(dsm) + 1024;

    const int tid = threadIdx.x, wid = tid >> 5, lane = tid & 31;
    const int warp_m = wid >> 2, warp_n = wid & 3;

    if (tid < 128) {
        int gr = m0 + tid;
        s_pair[tid] = (gr < M) ? g_list[e * T_TOK + gr] : -1;
    }
    __syncthreads();

    uint32_t offA[4], dstA[4]; bool vA[4];
    uint32_t offB[8], dstB[8];
    #pragma unroll
    for (int i = 0; i < 4; i++) {
        int c = tid + i * 256, r = c >> 3, cw = c & 7;
        int p = s_pair[r];
        vA[i] = (p >= 0);
        offA[i] = (uint32_t)(vA[i] ? p : 0) * INTER + cw * 8;
        dstA[i] = swz(r * 128 + cw * 16);
    }
    #pragma unroll
    for (int i = 0; i < 8; i++) {
        int c = tid + i * 256, r = c >> 3, cw = c & 7;
        offB[i] = ((uint32_t)e * HID + n0 + r) * INTER + cw * 8;
        dstB[i] = swz(r * 128 + cw * 16);
    }

    auto load_stage = [&](int b, int k0) {
        uint32_t st = TILE + b * STG;
        #pragma unroll
        for (int i = 0; i < 4; i++)
            cp16(st + dstA[i], g_hh + offA[i] + k0, vA[i]);
        #pragma unroll
        for (int i = 0; i < 8; i++)
            cp16(st + 16384 + dstB[i], g_w2h + offB[i] + k0, true);
        cp_commit();
    };

    float acc[4][8][4];
    #pragma unroll
    for (int m = 0; m < 4; m++)
        #pragma unroll
        for (int n = 0; n < 8; n++)
            #pragma unroll
            for (int k = 0; k < 4; k++) acc[m][n][k] = 0.f;

    const uint32_t a_row = warp_m * 64 + (lane & 15);
    const uint32_t a_kb  = (lane >> 4) * 16;
    const uint32_t b_row = warp_n * 64 + (lane & 7) + ((lane >> 4) << 3);
    const uint32_t b_kb  = ((lane >> 3) & 1) * 16;

    const int S = INTER / KSLAB;  // 8
    load_stage(0, 0);
    load_stage(1, KSLAB);
    load_stage(2, 2 * KSLAB);
    for (int s = 0; s < S; s++) {
        if (s + 2 < S) cp_wait<2>(); else if (s + 1 < S) cp_wait<1>(); else cp_wait<0>();
        __syncthreads();
        if (s + 3 < S) load_stage((s + 3) & 3, (s + 3) * KSLAB);
        const uint32_t st = TILE + (s & 3) * STG;
        const uint32_t sAh = st, sBh = st + 16384;
        #pragma unroll
        for (int ks = 0; ks < 4; ks++) {
            uint32_t ah[4][4];
            #pragma unroll
            for (int m = 0; m < 4; m++) {
                uint32_t off = (a_row + m * 16) * 128 + ks * 32 + a_kb;
                ldsm4(ah[m], sAh + swz(off));
            }
            #pragma unroll
            for (int j = 0; j < 4; j++) {
                uint32_t off = (b_row + j * 16) * 128 + ks * 32 + b_kb;
                uint32_t th[4];
                ldsm4(th, sBh + swz(off));
                #pragma unroll
                for (int m = 0; m < 4; m++) {
                    mma_f16(acc[m][2*j],   ah[m], th);
                    mma_f16(acc[m][2*j+1], ah[m], th + 2);
                }
            }
        }
    }

    const int g = lane >> 2, tg = lane & 3;
    #pragma unroll
    for (int m = 0; m < 4; m++) {
        int lr = warp_m * 64 + m * 16 + g;
        int p0 = s_pair[lr], p1 = s_pair[lr + 8];
        float w0 = (p0 >= 0) ? g_pairw[p0] : 0.f;
        float w1 = (p1 >= 0) ? g_pairw[p1] : 0.f;
        #pragma unroll
        for (int n = 0; n < 8; n++) {
            int col = n0 + warp_n * 64 + n * 8 + tg * 2;
            if (p0 >= 0)
                ((__half2*)g_y)[((uint32_t)p0 * HID + col) >> 1] =
                    __floats2half2_rn(w0 * acc[m][n][0], w0 * acc[m][n][1]);
            if (p1 >= 0)
                ((__half2*)g_y)[((uint32_t)p1 * HID + col) >> 1] =
                    __floats2half2_rn(w1 * acc[m][n][2], w1 * acc[m][n][3]);
        }
    }
}

// ---------------- deterministic 8-slot reduction (fp16 in, fp32 out) ----------------
__global__ void reduce_kernel(float* __restrict__ out) {
    size_t idx = (size_t)blockIdx.x * blockDim.x + threadIdx.x;
    const size_t total = (size_t)T_TOK * (HID / 8);
    if (idx >= total) return;
    size_t t = idx / (HID / 8);
    int    c = (int)(idx % (HID / 8));
    const __half* base = g_y + t * (size_t)TOPK * HID + c * 8;
    float s[8] = {0.f, 0.f, 0.f, 0.f, 0.f, 0.f, 0.f, 0.f};
    #pragma unroll
    for (int sl = 0; sl < TOPK; sl++) {
        uint4 v = *(const uint4*)(base + (size_t)sl * HID);
        const __half2* h2 = (const __half2*)&v;
        #pragma unroll
        for (int j = 0; j < 4; j++) {
            float2 f = __half22float2(h2[j]);
            s[2*j]     += f.x;
            s[2*j + 1] += f.y;
        }
    }
    float4* o4 = (float4*)(out + t * HID + c * 8);
    o4[0] = make_float4(s[0], s[1], s[2], s[3]);
    o4[1] = make_float4(s[4], s[5], s[6], s[7]);
}

extern "C" void kernel_launch(void* const* d_in, const int* in_sizes, int n_in,
                              void* d_out, int out_size) {
    (void)in_sizes; (void)n_in; (void)out_size;
    const float* x   = (const float*)d_in[0];
    const float* gw  = (const float*)d_in[1];
    const float* w13 = (const float*)d_in[2];
    const float* w2  = (const float*)d_in[3];
    float* out = (float*)d_out;

    cudaFuncSetAttribute(gemm1_mma, cudaFuncAttributeMaxDynamicSharedMemorySize, SMEMG);
    cudaFuncSetAttribute(gemm2_mma, cudaFuncAttributeMaxDynamicSharedMemorySize, SMEMG);

    const int n_cvt = (NEXP * N1 * HID + NEXP * HID * INTER) / 4;
    reset_kernel<<<1, 32>>>();
    cvt_x_kernel<<<(T_TOK * HID / 4 + 255) / 256, 256>>>(x);
    cvt_w_all<<<(n_cvt + 255) / 256, 256>>>(w13, w2);
    logits_kernel<<<T_TOK / 64, 256>>>(x, gw);
    topk_kernel<<<T_TOK / 8, 256>>>();
    gemm1_mma<<<dim3(INTER / 128, 64, NEXP), 256, SMEMG>>>();
    gemm2_mma<<<dim3(HID / 256, 64, NEXP), 256, SMEMG>>>();
    reduce_kernel<<<(int)(((size_t)T_TOK * (HID / 8)) / 256), 256>>>(out);
}